// round 3
// baseline (speedup 1.0000x reference)
#include <cuda_runtime.h>
#include <math.h>

#define Bn 16
#define Cn 64
#define Hn 32
#define Wn 32
#define Sn 1024
#define En 64
#define HEADSn 4
#define DHn 16
#define FFn 256
#define Lnum 3
#define CH_NO_UNIT 6
#define CH_INB 58
#define LN_EPS 1e-5f

// ---------------- scratch (device globals; no allocation) ----------------
__device__ float g_h[Bn * Sn * En];        // token states
__device__ float g_a[Bn * Sn * En];        // layernorm output
__device__ float g_qkv[Bn * Sn * 3 * En];  // fused qkv
__device__ float g_o[Bn * Sn * En];        // attention output
__device__ float g_ff[Bn * Sn * FFn];      // ff hidden
__device__ int g_order[Bn * Sn];           // squashed pos -> token
__device__ int g_inv[Bn * Sn];             // token -> squashed pos
__device__ int g_nkeep[Bn];

// ---------------- mask + stable partition (argsort of empty flag) --------
__global__ void mask_kernel(const float* __restrict__ x) {
    int b = blockIdx.x;
    int t = threadIdx.x;  // 1024 threads
    __shared__ int buf[2][Sn];
    float nu = x[(b * Cn + CH_NO_UNIT) * Sn + t];
    float ib = x[(b * Cn + CH_INB) * Sn + t];
    int empty = (nu != 0.0f) && (ib != 0.0f);
    int keep = empty ? 0 : 1;
    buf[0][t] = keep;
    __syncthreads();
    int cur = 0;
    for (int off = 1; off < Sn; off <<= 1) {
        int v = buf[cur][t];
        if (t >= off) v += buf[cur][t - off];
        buf[cur ^ 1][t] = v;
        __syncthreads();
        cur ^= 1;
    }
    int incl = buf[cur][t];
    int nk = buf[cur][Sn - 1];
    int excl = incl - keep;
    int pos = keep ? excl : (nk + (t - excl));
    g_inv[b * Sn + t] = pos;
    g_order[b * Sn + pos] = t;
    if (t == 0) g_nkeep[b] = nk;
}

// ---------------- embed: gather squashed features, project to E ----------
__global__ void embed_kernel(const float* __restrict__ x,
                             const float* __restrict__ ew,
                             const float* __restrict__ eb) {
    int s = blockIdx.x;
    int b = blockIdx.y;
    int e = threadIdx.x;  // 64 threads
    float* hrow = g_h + ((size_t)b * Sn + s) * En;
    int n = g_nkeep[b];
    if (s >= n) { hrow[e] = 0.0f; return; }
    __shared__ float f[66];
    int t = g_order[b * Sn + s];
    f[e] = x[((b * Cn) + e) * Sn + t];
    if (e == 0) {
        int hh = t / Wn, ww = t % Wn;
        f[64] = -1.0f + 2.0f * (float)ww / (float)(Wn - 1);  // pos[0,h,w]=lin[w]
        f[65] = -1.0f + 2.0f * (float)hh / (float)(Hn - 1);  // pos[1,h,w]=lin[h]
    }
    __syncthreads();
    float acc = eb[e];
#pragma unroll
    for (int c = 0; c < 66; c++) acc += f[c] * ew[c * En + e];
    hrow[e] = acc;
}

// ---------------- layernorm (warp per row, E=64) -------------------------
__global__ void ln_kernel(const float* __restrict__ in,
                          const float* __restrict__ w,
                          const float* __restrict__ bb,
                          float* __restrict__ out) {
    int row = blockIdx.x * 8 + (threadIdx.x >> 5);
    int lane = threadIdx.x & 31;
    const float* p = in + (size_t)row * En;
    float v0 = p[lane], v1 = p[lane + 32];
    float sum = v0 + v1;
#pragma unroll
    for (int o = 16; o; o >>= 1) sum += __shfl_xor_sync(0xFFFFFFFFu, sum, o);
    float mu = sum * (1.0f / 64.0f);
    float d0 = v0 - mu, d1 = v1 - mu;
    float vs = d0 * d0 + d1 * d1;
#pragma unroll
    for (int o = 16; o; o >>= 1) vs += __shfl_xor_sync(0xFFFFFFFFu, vs, o);
    float rs = rsqrtf(vs * (1.0f / 64.0f) + LN_EPS);
    float* q = out + (size_t)row * En;
    q[lane] = d0 * rs * w[lane] + bb[lane];
    q[lane + 32] = d1 * rs * w[lane + 32] + bb[lane + 32];
}

// ---------------- generic smem-tiled SGEMM -------------------------------
// C[M,N] = act(A[M,K] @ B + bias)  (optionally  C += ...)
// BT=true : B stored [N][K] (use row n as dot vector)   -> y = a @ B^T
// BT=false: B stored [K][N]                             -> y = a @ B
__device__ __forceinline__ float gelu_exact(float v) {
    return 0.5f * v * (1.0f + erff(v * 0.70710678118654752f));
}

template <bool BT, bool GELU, bool RES>
__global__ void sgemm_kernel(const float* __restrict__ A,
                             const float* __restrict__ B,
                             const float* __restrict__ bias,
                             float* __restrict__ C, int N, int K) {
    const int BK = 16;
    __shared__ float As[BK][64];
    __shared__ float Bs[BK][64];
    int tid = threadIdx.x;  // 256
    int row0 = blockIdx.y * 64, col0 = blockIdx.x * 64;
    int tr = (tid >> 4) << 2;   // 0..60
    int tc = (tid & 15) << 2;   // 0..60
    float acc[4][4];
#pragma unroll
    for (int i = 0; i < 4; i++)
#pragma unroll
        for (int j = 0; j < 4; j++) acc[i][j] = 0.0f;

    int ar = tid >> 2;          // 0..63
    int ac = (tid & 3) << 2;    // 0,4,8,12
    for (int k0 = 0; k0 < K; k0 += BK) {
        float4 av = *(const float4*)(A + (size_t)(row0 + ar) * K + k0 + ac);
        As[ac + 0][ar] = av.x; As[ac + 1][ar] = av.y;
        As[ac + 2][ar] = av.z; As[ac + 3][ar] = av.w;
        if (BT) {
            float4 bv = *(const float4*)(B + (size_t)(col0 + ar) * K + k0 + ac);
            Bs[ac + 0][ar] = bv.x; Bs[ac + 1][ar] = bv.y;
            Bs[ac + 2][ar] = bv.z; Bs[ac + 3][ar] = bv.w;
        } else {
            int bk = tid >> 4;          // 0..15
            int bn = (tid & 15) << 2;   // 0..60
            float4 bv = *(const float4*)(B + (size_t)(k0 + bk) * N + col0 + bn);
            *(float4*)&Bs[bk][bn] = bv;
        }
        __syncthreads();
#pragma unroll
        for (int kk = 0; kk < BK; kk++) {
            float a4[4], b4[4];
            *(float4*)a4 = *(const float4*)&As[kk][tr];
            *(float4*)b4 = *(const float4*)&Bs[kk][tc];
#pragma unroll
            for (int i = 0; i < 4; i++)
#pragma unroll
                for (int j = 0; j < 4; j++) acc[i][j] += a4[i] * b4[j];
        }
        __syncthreads();
    }
    float4 bv = *(const float4*)(bias + col0 + tc);
#pragma unroll
    for (int i = 0; i < 4; i++) {
        float4 v;
        v.x = acc[i][0] + bv.x; v.y = acc[i][1] + bv.y;
        v.z = acc[i][2] + bv.z; v.w = acc[i][3] + bv.w;
        if (GELU) {
            v.x = gelu_exact(v.x); v.y = gelu_exact(v.y);
            v.z = gelu_exact(v.z); v.w = gelu_exact(v.w);
        }
        float* cp = C + (size_t)(row0 + tr + i) * N + col0 + tc;
        if (RES) {
            float4 old = *(const float4*)cp;
            v.x += old.x; v.y += old.y; v.z += old.z; v.w += old.w;
        }
        *(float4*)cp = v;
    }
}

// ---------------- flash attention (thread per query, online softmax) -----
__global__ void attn_kernel() {
    int b = blockIdx.z, hh = blockIdx.y;
    int q = blockIdx.x * 128 + threadIdx.x;
    int n = g_nkeep[b];
    __shared__ float Ks[128][DHn];
    __shared__ float Vs[128][DHn];
    const float* qkv = g_qkv + (size_t)b * Sn * 192;

    float qr[DHn], o[DHn];
#pragma unroll
    for (int d = 0; d < DHn; d++) { qr[d] = 0.0f; o[d] = 0.0f; }
    bool valid = (q < n);
    if (valid) {
        const float* qp = qkv + (size_t)q * 192 + hh * DHn;
#pragma unroll
        for (int d = 0; d < DHn; d += 4) {
            float4 v = *(const float4*)(qp + d);
            qr[d] = v.x; qr[d + 1] = v.y; qr[d + 2] = v.z; qr[d + 3] = v.w;
        }
    }
    float m = -1e30f, l = 0.0f;
    for (int kb = 0; kb < n; kb += 128) {
        int kmax = min(128, n - kb);
        if ((int)threadIdx.x < kmax) {
            int kt = kb + threadIdx.x;
            const float* kp = qkv + (size_t)kt * 192 + 64 + hh * DHn;
            const float* vp = qkv + (size_t)kt * 192 + 128 + hh * DHn;
#pragma unroll
            for (int d = 0; d < DHn; d += 4) {
                *(float4*)&Ks[threadIdx.x][d] = *(const float4*)(kp + d);
                *(float4*)&Vs[threadIdx.x][d] = *(const float4*)(vp + d);
            }
        }
        __syncthreads();
        if (valid) {
            for (int k = 0; k < kmax; k++) {
                float s = 0.0f;
#pragma unroll
                for (int d = 0; d < DHn; d++) s += qr[d] * Ks[k][d];
                s *= 0.25f;  // 1/sqrt(16)
                if (s <= m) {
                    float p = __expf(s - m);
                    l += p;
#pragma unroll
                    for (int d = 0; d < DHn; d++) o[d] += p * Vs[k][d];
                } else {
                    float c = __expf(m - s);
                    l = l * c + 1.0f;
#pragma unroll
                    for (int d = 0; d < DHn; d++) o[d] = o[d] * c + Vs[k][d];
                    m = s;
                }
            }
        }
        __syncthreads();
    }
    if (q < Sn) {
        float inv_l = valid ? (1.0f / l) : 0.0f;
        float* op = g_o + ((size_t)b * Sn + q) * En + hh * DHn;
#pragma unroll
        for (int d = 0; d < DHn; d += 4) {
            float4 v;
            v.x = o[d] * inv_l; v.y = o[d + 1] * inv_l;
            v.z = o[d + 2] * inv_l; v.w = o[d + 3] * inv_l;
            *(float4*)(op + d) = v;
        }
    }
}

// ---------------- unsquash: inverse perm + keep mask + transpose ---------
__global__ void unsquash_kernel(float* __restrict__ out) {
    int idx = blockIdx.x * 256 + threadIdx.x;  // over B*E*S
    int t = idx & (Sn - 1);
    int be = idx >> 10;
    int b = be >> 6;
    int e = be & 63;
    int pos = g_inv[b * Sn + t];
    int n = g_nkeep[b];
    out[idx] = (pos < n) ? g_h[((size_t)b * Sn + pos) * En + e] : 0.0f;
}

// ---------------- host driver --------------------------------------------
extern "C" void kernel_launch(void* const* d_in, const int* in_sizes, int n_in,
                              void* d_out, int out_size) {
    const float* x = (const float*)d_in[0];
    const float* embed_w = (const float*)d_in[1];
    const float* embed_b = (const float*)d_in[2];
    const float* ln1_w = (const float*)d_in[3];
    const float* ln1_b = (const float*)d_in[4];
    const float* in_proj_w = (const float*)d_in[5];
    const float* in_proj_b = (const float*)d_in[6];
    const float* out_w = (const float*)d_in[7];
    const float* out_b = (const float*)d_in[8];
    const float* ln2_w = (const float*)d_in[9];
    const float* ln2_b = (const float*)d_in[10];
    const float* ff1_w = (const float*)d_in[11];
    const float* ff1_b = (const float*)d_in[12];
    const float* ff2_w = (const float*)d_in[13];
    const float* ff2_b = (const float*)d_in[14];
    float* out = (float*)d_out;

    float *h_, *a_, *qkv_, *o_, *ff_;
    cudaGetSymbolAddress((void**)&h_, g_h);
    cudaGetSymbolAddress((void**)&a_, g_a);
    cudaGetSymbolAddress((void**)&qkv_, g_qkv);
    cudaGetSymbolAddress((void**)&o_, g_o);
    cudaGetSymbolAddress((void**)&ff_, g_ff);

    const int M = Bn * Sn;  // 16384 token rows

    mask_kernel<<<Bn, Sn>>>(x);
    embed_kernel<<<dim3(Sn, Bn), 64>>>(x, embed_w, embed_b);

    for (int l = 0; l < Lnum; l++) {
        // pre-norm attention
        ln_kernel<<<M / 8, 256>>>(h_, ln1_w + l * En, ln1_b + l * En, a_);
        sgemm_kernel<true, false, false><<<dim3(3, M / 64), 256>>>(
            a_, in_proj_w + (size_t)l * 3 * En * En, in_proj_b + l * 3 * En,
            qkv_, 3 * En, En);
        attn_kernel<<<dim3(Sn / 128, HEADSn, Bn), 128>>>();
        sgemm_kernel<true, false, true><<<dim3(1, M / 64), 256>>>(
            o_, out_w + (size_t)l * En * En, out_b + l * En, h_, En, En);
        // pre-norm feed-forward
        ln_kernel<<<M / 8, 256>>>(h_, ln2_w + l * En, ln2_b + l * En, a_);
        sgemm_kernel<false, true, false><<<dim3(FFn / 64, M / 64), 256>>>(
            a_, ff1_w + (size_t)l * En * FFn, ff1_b + l * FFn, ff_, FFn, En);
        sgemm_kernel<false, false, true><<<dim3(1, M / 64), 256>>>(
            ff_, ff2_w + (size_t)l * FFn * En, ff2_b + l * En, h_, En, FFn);
    }

    unsquash_kernel<<<(Bn * En * Sn) / 256, 256>>>(out);
}